// round 3
// baseline (speedup 1.0000x reference)
#include <cuda_runtime.h>

typedef unsigned long long ULL;

__device__ __forceinline__ ULL fma2(ULL a, ULL b, ULL c) {
    ULL d;
    asm("fma.rn.f32x2 %0, %1, %2, %3;" : "=l"(d) : "l"(a), "l"(b), "l"(c));
    return d;
}
__device__ __forceinline__ ULL dup2(float x) {
    ULL d;
    asm("mov.b64 %0, {%1, %1};" : "=l"(d) : "f"(x));
    return d;
}
__device__ __forceinline__ float2 unpk(ULL v) {
    float2 r;
    asm("mov.b64 {%0, %1}, %2;" : "=f"(r.x), "=f"(r.y) : "l"(v));
    return r;
}

#define N_TOT 8192
#define TN 8          // n's per attention block

// Scratch (static device globals — no allocation)
__device__ float2 g_ca2T[16 * 512];    // [k][p] : (ca[p][2k], ca[p][2k+1])
__device__ float2 g_qa2[N_TOT * 16];   // [n][k] : (qa[n][2k], qa[n][2k+1])
__device__ float  g_c[N_TOT * 16];     // pooled-projection output c (N,16)

// ---------------------------------------------------------------------------
__global__ void pre_ca(const float* __restrict__ cx, const float* __restrict__ Wa1) {
    int idx = blockIdx.x * blockDim.x + threadIdx.x;   // 8192 = 512p * 16k
    int p = idx & 511, k = idx >> 9;
    float x0 = cx[p * 2 + 0], x1 = cx[p * 2 + 1];
    float c0 = x0 * Wa1[64 + 2 * k]     + x1 * Wa1[96 + 2 * k];
    float c1 = x0 * Wa1[64 + 2 * k + 1] + x1 * Wa1[96 + 2 * k + 1];
    g_ca2T[k * 512 + p] = make_float2(c0, c1);
}

__global__ void pre_qa(const float* __restrict__ r, const float* __restrict__ Wa1) {
    int idx = blockIdx.x * blockDim.x + threadIdx.x;   // 131072 = 8192n * 16k
    int n = idx >> 4, k = idx & 15;
    float x0 = r[n * 4 + 0], x1 = r[n * 4 + 1];
    float q0 = x0 * Wa1[2 * k]     + x1 * Wa1[32 + 2 * k];
    float q1 = x0 * Wa1[2 * k + 1] + x1 * Wa1[32 + 2 * k + 1];
    g_qa2[n * 16 + k] = make_float2(q0, q1);
}

// ---------------------------------------------------------------------------
// Attention: block handles TN consecutive n's; thread = p (P=512).
// ca register-resident for the whole block; logits staged to shared; ONE
// batched epilogue: softmax + weighted pooling + 4->32->16 projection.
__global__ __launch_bounds__(512) void attn_kernel(
    const float* __restrict__ coeff_y,
    const float* __restrict__ Wa2,
    const float* __restrict__ Wa3,
    const float* __restrict__ Wp1, const float* __restrict__ bp1,
    const float* __restrict__ Wp2, const float* __restrict__ bp2)
{
    __shared__ __align__(16) float sWa2[1024];
    __shared__ float sLog[TN][512];
    __shared__ float sMax[TN * 16];
    __shared__ float sGm[TN];
    __shared__ float sRed[16][TN][5];
    __shared__ float sPool[TN][5];
    __shared__ float sHp[TN][32];

    const int tid  = threadIdx.x;
    const int lane = tid & 31, warp = tid >> 5;

    sWa2[tid]       = Wa2[tid];
    sWa2[tid + 512] = Wa2[tid + 512];
    const int n0 = blockIdx.x * TN;

    // ca for this thread's p, register-resident for the whole block
    float2 ca[16];
#pragma unroll
    for (int k = 0; k < 16; ++k) ca[k] = g_ca2T[k * 512 + tid];
    __syncthreads();

#pragma unroll 1
    for (int t = 0; t < TN; ++t) {
        const int n = n0 + t;
        const float4* qa4 = reinterpret_cast<const float4*>(g_qa2 + n * 16);

        ULL acc[16];
#pragma unroll
        for (int q = 0; q < 16; ++q) acc[q] = 0ull;

#pragma unroll
        for (int k2 = 0; k2 < 8; ++k2) {
            float4 qa = qa4[k2];          // broadcast L1-hit
            {   // k = 2*k2
                int k = 2 * k2;
                ULL dlo = dup2(fmaxf(qa.x + ca[k].x, 0.f));
                ULL dhi = dup2(fmaxf(qa.y + ca[k].y, 0.f));
                const ulonglong2* r0 = reinterpret_cast<const ulonglong2*>(sWa2 + 64 * k);
#pragma unroll
                for (int q = 0; q < 8; ++q) {
                    ulonglong2 w0 = r0[q];
                    ulonglong2 w1 = r0[q + 8];
                    acc[2 * q]     = fma2(dlo, w0.x, acc[2 * q]);
                    acc[2 * q + 1] = fma2(dlo, w0.y, acc[2 * q + 1]);
                    acc[2 * q]     = fma2(dhi, w1.x, acc[2 * q]);
                    acc[2 * q + 1] = fma2(dhi, w1.y, acc[2 * q + 1]);
                }
            }
            {   // k = 2*k2+1
                int k = 2 * k2 + 1;
                ULL dlo = dup2(fmaxf(qa.z + ca[k].x, 0.f));
                ULL dhi = dup2(fmaxf(qa.w + ca[k].y, 0.f));
                const ulonglong2* r0 = reinterpret_cast<const ulonglong2*>(sWa2 + 64 * k);
#pragma unroll
                for (int q = 0; q < 8; ++q) {
                    ulonglong2 w0 = r0[q];
                    ulonglong2 w1 = r0[q + 8];
                    acc[2 * q]     = fma2(dlo, w0.x, acc[2 * q]);
                    acc[2 * q + 1] = fma2(dlo, w0.y, acc[2 * q + 1]);
                    acc[2 * q]     = fma2(dhi, w1.x, acc[2 * q]);
                    acc[2 * q + 1] = fma2(dhi, w1.y, acc[2 * q + 1]);
                }
            }
        }

        float logit = 0.f;
#pragma unroll
        for (int q = 0; q < 16; ++q) {
            float2 a = unpk(acc[q]);
            float2 w = reinterpret_cast<const float2*>(Wa3)[q];
            logit += fmaxf(a.x, 0.f) * w.x + fmaxf(a.y, 0.f) * w.y;
        }
        sLog[t][tid] = logit;

        // per-warp max for this t (no barrier needed; warp-local)
        float m = logit;
#pragma unroll
        for (int off = 16; off; off >>= 1)
            m = fmaxf(m, __shfl_xor_sync(0xffffffffu, m, off));
        if (lane == 0) sMax[t * 16 + warp] = m;
    }
    __syncthreads();

    if (tid < TN) {
        float gm = sMax[tid * 16];
#pragma unroll
        for (int w = 1; w < 16; ++w) gm = fmaxf(gm, sMax[tid * 16 + w]);
        sGm[tid] = gm;
    }
    __syncthreads();

    const float4 cy = reinterpret_cast<const float4*>(coeff_y)[tid];

#pragma unroll 1
    for (int t = 0; t < TN; ++t) {
        float e = __expf(sLog[t][tid] - sGm[t]);
        float v0 = e, v1 = e * cy.x, v2 = e * cy.y, v3 = e * cy.z, v4 = e * cy.w;
#pragma unroll
        for (int off = 16; off; off >>= 1) {
            v0 += __shfl_xor_sync(0xffffffffu, v0, off);
            v1 += __shfl_xor_sync(0xffffffffu, v1, off);
            v2 += __shfl_xor_sync(0xffffffffu, v2, off);
            v3 += __shfl_xor_sync(0xffffffffu, v3, off);
            v4 += __shfl_xor_sync(0xffffffffu, v4, off);
        }
        if (lane == 0) {
            sRed[warp][t][0] = v0; sRed[warp][t][1] = v1; sRed[warp][t][2] = v2;
            sRed[warp][t][3] = v3; sRed[warp][t][4] = v4;
        }
    }
    __syncthreads();
    if (tid < TN * 5) {
        int t = tid / 5, j = tid % 5;
        float s = 0.f;
#pragma unroll
        for (int w = 0; w < 16; ++w) s += sRed[w][t][j];
        sPool[t][j] = s;
    }
    __syncthreads();

    // pooled projection stage 1: hp[t][32]
    if (tid < TN * 32) {
        int t = tid >> 5, j = tid & 31;
        float inv = 1.f / sPool[t][0];
        float a0 = sPool[t][1] * inv, a1 = sPool[t][2] * inv;
        float a2 = sPool[t][3] * inv, a3 = sPool[t][4] * inv;
        float hp = bp1[j] + a0 * Wp1[j] + a1 * Wp1[32 + j]
                          + a2 * Wp1[64 + j] + a3 * Wp1[96 + j];
        sHp[t][j] = fmaxf(hp, 0.f);
    }
    __syncthreads();
    // stage 2: c[t][16]
    if (tid < TN * 16) {
        int t = tid >> 4, j = tid & 15;
        float cv = bp2[j];
#pragma unroll
        for (int k2 = 0; k2 < 32; ++k2) cv += sHp[t][k2] * Wp2[k2 * 16 + j];
        g_c[(n0 + t) * 16 + j] = cv;
    }
}

// ---------------------------------------------------------------------------
// Gating: block = 32 rows, 256 threads. Stage B: thread = 4 rows x 8 j.
// Warp w owns rows 4w..4w+3 entirely -> epilogue is warp-local shuffle reduce.
__global__ __launch_bounds__(256) void gate_kernel(
    const float* __restrict__ r, const float* __restrict__ rp,
    const float* __restrict__ Wg1, const float* __restrict__ bg1,
    const float* __restrict__ Wg2, const float* __restrict__ bg2,
    const float* __restrict__ Wg3, const float* __restrict__ bg3,
    float* __restrict__ out)
{
    __shared__ float sX[32][25];
    __shared__ __align__(16) float sG1[256 * 32];   // [k][row]

    const int tid  = threadIdx.x;
    const int lane = tid & 31, warp = tid >> 5;
    const int n0 = blockIdx.x * 32;

    for (int idx = tid; idx < 32 * 24; idx += 256) {
        int row = idx / 24, j = idx % 24;
        int n = n0 + row;
        float v = (j < 4) ? r[n * 4 + j]
                : (j < 8) ? rp[n * 4 + (j - 4)]
                          : g_c[n * 16 + (j - 8)];
        sX[row][j] = v;
    }
    __syncthreads();

    // Stage A: G1 = relu(X @ Wg1 + bg1); warp w covers k in [32w, 32w+32), row = lane
    {
        float x[24];
#pragma unroll
        for (int j = 0; j < 24; ++j) x[j] = sX[lane][j];
        const int kbase = warp * 32;
        for (int kk = 0; kk < 32; ++kk) {
            int k = kbase + kk;
            float a = bg1[k];
#pragma unroll
            for (int j = 0; j < 24; ++j) a += x[j] * Wg1[j * 256 + k];
            sG1[k * 32 + lane] = fmaxf(a, 0.f);
        }
    }
    __syncthreads();

    // Stage B: warp w -> rows r0=4w..4w+3; lane -> j block [8*lane, 8*lane+8)
    const int jb = lane * 8;
    const int r0 = warp * 4;

    ULL bj[4];
    {
        const ulonglong2* b = reinterpret_cast<const ulonglong2*>(bg2 + jb);
        ulonglong2 b0 = b[0], b1 = b[1];
        bj[0] = b0.x; bj[1] = b0.y; bj[2] = b1.x; bj[3] = b1.y;
    }
    ULL acc[4][4];
#pragma unroll
    for (int i = 0; i < 4; ++i)
#pragma unroll
        for (int q = 0; q < 4; ++q) acc[i][q] = bj[q];

#pragma unroll 4
    for (int k = 0; k < 256; ++k) {
        float4 g = *reinterpret_cast<const float4*>(sG1 + k * 32 + r0); // broadcast
        ULL d0 = dup2(g.x), d1 = dup2(g.y), d2 = dup2(g.z), d3 = dup2(g.w);
        const ulonglong2* w = reinterpret_cast<const ulonglong2*>(Wg2 + k * 256 + jb);
        ulonglong2 w01 = w[0], w23 = w[1];   // coalesced across warp
        acc[0][0] = fma2(d0, w01.x, acc[0][0]);
        acc[0][1] = fma2(d0, w01.y, acc[0][1]);
        acc[0][2] = fma2(d0, w23.x, acc[0][2]);
        acc[0][3] = fma2(d0, w23.y, acc[0][3]);
        acc[1][0] = fma2(d1, w01.x, acc[1][0]);
        acc[1][1] = fma2(d1, w01.y, acc[1][1]);
        acc[1][2] = fma2(d1, w23.x, acc[1][2]);
        acc[1][3] = fma2(d1, w23.y, acc[1][3]);
        acc[2][0] = fma2(d2, w01.x, acc[2][0]);
        acc[2][1] = fma2(d2, w01.y, acc[2][1]);
        acc[2][2] = fma2(d2, w23.x, acc[2][2]);
        acc[2][3] = fma2(d2, w23.y, acc[2][3]);
        acc[3][0] = fma2(d3, w01.x, acc[3][0]);
        acc[3][1] = fma2(d3, w01.y, acc[3][1]);
        acc[3][2] = fma2(d3, w23.x, acc[3][2]);
        acc[3][3] = fma2(d3, w23.y, acc[3][3]);
    }

    // epilogue: relu -> dot with Wg3 slice -> warp reduce (rows are warp-local)
    float2 w3[4];
    {
        const float2* w3p = reinterpret_cast<const float2*>(Wg3 + jb);
        w3[0] = w3p[0]; w3[1] = w3p[1]; w3[2] = w3p[2]; w3[3] = w3p[3];
    }
    float part[4];
#pragma unroll
    for (int i = 0; i < 4; ++i) {
        float s = 0.f;
#pragma unroll
        for (int q = 0; q < 4; ++q) {
            float2 a = unpk(acc[i][q]);
            s += fmaxf(a.x, 0.f) * w3[q].x + fmaxf(a.y, 0.f) * w3[q].y;
        }
        part[i] = s;
    }
#pragma unroll
    for (int off = 16; off; off >>= 1) {
#pragma unroll
        for (int i = 0; i < 4; ++i)
            part[i] += __shfl_xor_sync(0xffffffffu, part[i], off);
    }
    if (lane == 0) {
        float b3 = bg3[0];
#pragma unroll
        for (int i = 0; i < 4; ++i)
            out[n0 + r0 + i] = __expf(part[i] + b3);
    }
}

// ---------------------------------------------------------------------------
extern "C" void kernel_launch(void* const* d_in, const int* in_sizes, int n_in,
                              void* d_out, int out_size) {
    (void)in_sizes; (void)n_in; (void)out_size;
    const float* r   = (const float*)d_in[0];
    const float* rp  = (const float*)d_in[1];
    const float* cx  = (const float*)d_in[2];
    const float* cy  = (const float*)d_in[3];
    const float* Wa1 = (const float*)d_in[4];
    const float* Wa2 = (const float*)d_in[5];
    const float* Wa3 = (const float*)d_in[6];
    const float* Wp1 = (const float*)d_in[7];
    const float* bp1 = (const float*)d_in[8];
    const float* Wp2 = (const float*)d_in[9];
    const float* bp2 = (const float*)d_in[10];
    const float* Wg1 = (const float*)d_in[11];
    const float* bg1 = (const float*)d_in[12];
    const float* Wg2 = (const float*)d_in[13];
    const float* bg2 = (const float*)d_in[14];
    const float* Wg3 = (const float*)d_in[15];
    const float* bg3 = (const float*)d_in[16];
    float* out = (float*)d_out;

    pre_ca<<<16, 512>>>(cx, Wa1);
    pre_qa<<<512, 256>>>(r, Wa1);
    attn_kernel<<<N_TOT / TN, 512>>>(cy, Wa2, Wa3, Wp1, bp1, Wp2, bp2);
    gate_kernel<<<N_TOT / 32, 256>>>(r, rp, Wg1, bg1, Wg2, bg2, Wg3, bg3, out);
}